// round 1
// baseline (speedup 1.0000x reference)
#include <cuda_runtime.h>
#include <math.h>

// Problem constants
#define BN 4
#define HH 128
#define WW 128
#define HWS (HH * WW)
#define CC 64          // c2 = 2*hid
#define O1 64
#define O2 32
#define NOFF 27
#define NOFFP 28       // padded to multiple of 4

// ---------------- device scratch (no allocations allowed) ----------------
__device__ float g_x1[BN * CC * HWS];      // concat(pB,pA), layer1 input  (16MB)
__device__ float g_x2[BN * CC * HWS];      // layer1 output                 (16MB)
__device__ float g_off[BN * NOFF * HWS];   // offset conv output            (7MB)
__device__ float g_wo1[CC * 9 * NOFFP];    // offset weights reordered [c][k][o-pad]
__device__ float g_wo2[CC * 9 * NOFFP];
__device__ float g_wr1[9 * CC * O1];       // main weights reordered+BN-folded [k][c][o]
__device__ float g_wr2[9 * CC * O2];
__device__ float g_b1[O1];                 // BN-folded bias
__device__ float g_b2[O2];
__device__ float g_bo1[NOFFP];
__device__ float g_bo2[NOFFP];

// ---------------- prep: concat, weight reorder, BN fold ----------------
__global__ void prep_kernel(
    const float* __restrict__ pA, const float* __restrict__ pB,
    const float* __restrict__ wo1, const float* __restrict__ bo1,
    const float* __restrict__ w1, const float* __restrict__ g1,
    const float* __restrict__ be1, const float* __restrict__ rm1, const float* __restrict__ rv1,
    const float* __restrict__ wo2, const float* __restrict__ bo2,
    const float* __restrict__ w2, const float* __restrict__ g2,
    const float* __restrict__ be2, const float* __restrict__ rm2, const float* __restrict__ rv2)
{
    int t = blockIdx.x * blockDim.x + threadIdx.x;
    int stride = gridDim.x * blockDim.x;

    // concat: channels 0..31 = pB, 32..63 = pA
    for (int i = t; i < BN * CC * HWS; i += stride) {
        int b = i / (CC * HWS);
        int r = i % (CC * HWS);
        int c = r / HWS;
        int s = r % HWS;
        g_x1[i] = (c < 32) ? pB[(b * 32 + c) * HWS + s]
                           : pA[(b * 32 + (c - 32)) * HWS + s];
    }

    // offset weights: g_wo[(c*9+k)*28 + o] = wo[(o*CC+c)*9 + k], pad o=27 with 0
    for (int i = t; i < CC * 9 * NOFFP; i += stride) {
        int o = i % NOFFP;
        int ck = i / NOFFP;
        int k = ck % 9;
        int c = ck / 9;
        g_wo1[i] = (o < NOFF) ? wo1[(o * CC + c) * 9 + k] : 0.f;
        g_wo2[i] = (o < NOFF) ? wo2[(o * CC + c) * 9 + k] : 0.f;
    }
    if (t < NOFFP) {
        g_bo1[t] = (t < NOFF) ? bo1[t] : 0.f;
        g_bo2[t] = (t < NOFF) ? bo2[t] : 0.f;
    }

    // main weights: g_wr[(k*CC+c)*O + o] = w[(o*CC+c)*9 + k] * inv[o]
    for (int i = t; i < 9 * CC * O1; i += stride) {
        int o = i % O1;
        int kc = i / O1;
        int c = kc % CC;
        int k = kc / CC;
        float inv = g1[o] * rsqrtf(rv1[o] + 1e-5f);
        g_wr1[i] = w1[(o * CC + c) * 9 + k] * inv;
    }
    for (int i = t; i < 9 * CC * O2; i += stride) {
        int o = i % O2;
        int kc = i / O2;
        int c = kc % CC;
        int k = kc / CC;
        float inv = g2[o] * rsqrtf(rv2[o] + 1e-5f);
        g_wr2[i] = w2[(o * CC + c) * 9 + k] * inv;
    }
    if (t < O1) { float inv = g1[t] * rsqrtf(rv1[t] + 1e-5f); g_b1[t] = be1[t] - rm1[t] * inv; }
    if (t < O2) { float inv = g2[t] * rsqrtf(rv2[t] + 1e-5f); g_b2[t] = be2[t] - rm2[t] * inv; }
}

// ---------------- offset conv: 3x3, CC->27, zero-pad 1 ----------------
__global__ __launch_bounds__(256)
void offconv_kernel(const float* __restrict__ xin,
                    const float* __restrict__ wo,   // reordered [c][k][o-pad28]
                    const float* __restrict__ bo)   // [28]
{
    extern __shared__ float sw[];                    // CC*9*28 floats = 63KB
    for (int i = threadIdx.x; i < CC * 9 * NOFFP; i += blockDim.x) sw[i] = wo[i];
    __syncthreads();

    int t = blockIdx.x * blockDim.x + threadIdx.x;
    if (t >= BN * HWS) return;
    int b = t / HWS;
    int s = t % HWS;
    int h = s / WW;
    int w = s % WW;

    float acc[NOFFP];
#pragma unroll
    for (int o = 0; o < NOFFP; o++) acc[o] = bo[o];

    const float* xb = xin + b * CC * HWS;
#pragma unroll 1
    for (int c = 0; c < CC; c++) {
        const float* xc = xb + c * HWS;
        float v[9];
#pragma unroll
        for (int r = 0; r < 3; r++) {
            int y = h + r - 1;
#pragma unroll
            for (int q = 0; q < 3; q++) {
                int xx = w + q - 1;
                v[r * 3 + q] = (y >= 0 && y < HH && xx >= 0 && xx < WW) ? xc[y * WW + xx] : 0.f;
            }
        }
        const float4* wp = (const float4*)(sw + c * 9 * NOFFP);
#pragma unroll
        for (int k = 0; k < 9; k++) {
            float vv = v[k];
#pragma unroll
            for (int o4 = 0; o4 < NOFFP / 4; o4++) {
                float4 wv = wp[k * (NOFFP / 4) + o4];
                acc[o4 * 4 + 0] += vv * wv.x;
                acc[o4 * 4 + 1] += vv * wv.y;
                acc[o4 * 4 + 2] += vv * wv.z;
                acc[o4 * 4 + 3] += vv * wv.w;
            }
        }
    }
    float* ob = g_off + b * NOFF * HWS + s;
#pragma unroll
    for (int o = 0; o < NOFF; o++) ob[o * HWS] = acc[o];
}

// ---------------- deform sample + einsum + (BN folded) + relu [+ gate] ----------------
template <int O, bool FUSE_OUT>
__global__ __launch_bounds__(256)
void deform_kernel(const float* __restrict__ xin,
                   const float* __restrict__ wr,    // [k][c][o], BN-scaled
                   const float* __restrict__ bias,  // [O], BN-folded
                   float* __restrict__ out,
                   const float* __restrict__ Aatt,
                   const float* __restrict__ Batt)
{
    extern __shared__ float sw[];                    // 9*CC*O floats
    for (int i = threadIdx.x; i < 9 * CC * O; i += blockDim.x) sw[i] = wr[i];
    __syncthreads();

    int t = blockIdx.x * blockDim.x + threadIdx.x;
    if (t >= BN * HWS) return;
    int b = t / HWS;
    int s = t % HWS;
    int h = s / WW;
    int w = s % WW;

    const float* offp = g_off + b * NOFF * HWS + s;

    float acc[O];
#pragma unroll
    for (int o = 0; o < O; o++) acc[o] = bias[o];

    const float* xb = xin + b * CC * HWS;

#pragma unroll 1
    for (int k = 0; k < 9; k++) {
        float dy = offp[(2 * k) * HWS];
        float dx = offp[(2 * k + 1) * HWS];
        float mr = offp[(18 + k) * HWS];
        float m = 1.f / (1.f + expf(-mr));

        float ys = (float)h + (float)(k / 3 - 1) + dy;
        float xs = (float)w + (float)(k % 3 - 1) + dx;
        float y0f = floorf(ys), x0f = floorf(xs);
        float fy = ys - y0f, fx = xs - x0f;
        int y0 = (int)y0f, x0 = (int)x0f;
        int y1 = y0 + 1, x1 = x0 + 1;

        float vy0 = (y0 >= 0 && y0 < HH) ? 1.f : 0.f;
        float vy1 = (y1 >= 0 && y1 < HH) ? 1.f : 0.f;
        float vx0 = (x0 >= 0 && x0 < WW) ? 1.f : 0.f;
        float vx1 = (x1 >= 0 && x1 < WW) ? 1.f : 0.f;

        float w00 = (1.f - fy) * (1.f - fx) * m * vy0 * vx0;
        float w01 = (1.f - fy) * fx * m * vy0 * vx1;
        float w10 = fy * (1.f - fx) * m * vy1 * vx0;
        float w11 = fy * fx * m * vy1 * vx1;

        int cy0 = min(max(y0, 0), HH - 1), cy1 = min(max(y1, 0), HH - 1);
        int cx0 = min(max(x0, 0), WW - 1), cx1 = min(max(x1, 0), WW - 1);
        int i00 = cy0 * WW + cx0, i01 = cy0 * WW + cx1;
        int i10 = cy1 * WW + cx0, i11 = cy1 * WW + cx1;

        const float* swk = sw + k * CC * O;
#pragma unroll 2
        for (int c = 0; c < CC; c++) {
            const float* xc = xb + c * HWS;
            float val = w00 * xc[i00] + w01 * xc[i01] + w10 * xc[i10] + w11 * xc[i11];
            const float4* wp = (const float4*)(swk + c * O);
#pragma unroll
            for (int o4 = 0; o4 < O / 4; o4++) {
                float4 wv = wp[o4];
                acc[o4 * 4 + 0] += val * wv.x;
                acc[o4 * 4 + 1] += val * wv.y;
                acc[o4 * 4 + 2] += val * wv.z;
                acc[o4 * 4 + 3] += val * wv.w;
            }
        }
    }

    if (FUSE_OUT) {
        float ga = (1.f - Aatt[b * HWS + s]) * Batt[b * HWS + s];
#pragma unroll
        for (int o = 0; o < O; o++)
            out[(b * O + o) * HWS + s] = fmaxf(acc[o], 0.f) * ga;
    } else {
#pragma unroll
        for (int o = 0; o < O; o++)
            out[(b * O + o) * HWS + s] = fmaxf(acc[o], 0.f);
    }
}

// ---------------- launch ----------------
extern "C" void kernel_launch(void* const* d_in, const int* in_sizes, int n_in,
                              void* d_out, int out_size)
{
    const float* pA   = (const float*)d_in[1];
    const float* pB   = (const float*)d_in[2];
    const float* Aatt = (const float*)d_in[3];
    const float* Batt = (const float*)d_in[4];
    const float* wo1  = (const float*)d_in[5];
    const float* bo1  = (const float*)d_in[6];
    const float* w1   = (const float*)d_in[7];
    const float* g1   = (const float*)d_in[8];
    const float* be1  = (const float*)d_in[9];
    const float* rm1  = (const float*)d_in[10];
    const float* rv1  = (const float*)d_in[11];
    const float* wo2  = (const float*)d_in[12];
    const float* bo2  = (const float*)d_in[13];
    const float* w2   = (const float*)d_in[14];
    const float* g2   = (const float*)d_in[15];
    const float* be2  = (const float*)d_in[16];
    const float* rm2  = (const float*)d_in[17];
    const float* rv2  = (const float*)d_in[18];

    float *x1, *x2, *pwo1, *pwo2, *pwr1, *pwr2, *pb1, *pb2, *pbo1, *pbo2;
    cudaGetSymbolAddress((void**)&x1,  g_x1);
    cudaGetSymbolAddress((void**)&x2,  g_x2);
    cudaGetSymbolAddress((void**)&pwo1, g_wo1);
    cudaGetSymbolAddress((void**)&pwo2, g_wo2);
    cudaGetSymbolAddress((void**)&pwr1, g_wr1);
    cudaGetSymbolAddress((void**)&pwr2, g_wr2);
    cudaGetSymbolAddress((void**)&pb1,  g_b1);
    cudaGetSymbolAddress((void**)&pb2,  g_b2);
    cudaGetSymbolAddress((void**)&pbo1, g_bo1);
    cudaGetSymbolAddress((void**)&pbo2, g_bo2);

    const int smem_off = CC * 9 * NOFFP * 4;         // 64512 B
    const int smem_d1  = 9 * CC * O1 * 4;            // 147456 B
    const int smem_d2  = 9 * CC * O2 * 4;            // 73728 B
    cudaFuncSetAttribute(offconv_kernel, cudaFuncAttributeMaxDynamicSharedMemorySize, smem_off);
    cudaFuncSetAttribute(deform_kernel<O1, false>, cudaFuncAttributeMaxDynamicSharedMemorySize, smem_d1);
    cudaFuncSetAttribute(deform_kernel<O2, true>,  cudaFuncAttributeMaxDynamicSharedMemorySize, smem_d2);

    const int npix = BN * HWS;                       // 65536
    dim3 blk(256);
    dim3 grd((npix + 255) / 256);

    prep_kernel<<<256, 256>>>(pA, pB, wo1, bo1, w1, g1, be1, rm1, rv1,
                              wo2, bo2, w2, g2, be2, rm2, rv2);

    offconv_kernel<<<grd, blk, smem_off>>>(x1, pwo1, pbo1);
    deform_kernel<O1, false><<<grd, blk, smem_d1>>>(x1, pwr1, pb1, x2, nullptr, nullptr);
    offconv_kernel<<<grd, blk, smem_off>>>(x2, pwo2, pbo2);
    deform_kernel<O2, true><<<grd, blk, smem_d2>>>(x2, pwr2, pb2, (float*)d_out, Aatt, Batt);
}